// round 9
// baseline (speedup 1.0000x reference)
#include <cuda_runtime.h>
#include <cuda_bf16.h>

#define BB 1024
#define II 256
#define HH 256
#define TT 64
#define TM1 63

// ---------------- device scratch (static: no allocation allowed) ----------------
__device__ __nv_bfloat16 g_prefsb[(size_t)BB * II * TT];   // [b][i][u] bf16, 32 MB (transposed!)
__device__ float g_h[2][BB * HH];
__device__ float g_c[2][BB * HH];
// A = [w_in | h] as bf16 hi/lo split, double-buffered on the h half: [slot][b][k0..511]
__device__ __nv_bfloat16 g_Ahi[2][(size_t)BB * 512];
__device__ __nv_bfloat16 g_Alo[2][(size_t)BB * 512];
// W = [W_ih | W_hh] rows n=gate*256+j, k 0..511, bf16 hi/lo split
__device__ __nv_bfloat16 g_Whi[(size_t)1024 * 512];
__device__ __nv_bfloat16 g_Wlo[(size_t)1024 * 512];
// W_h transposed [u][k] bf16 (hi only; error << s-bf16 quantization)
__device__ __nv_bfloat16 g_WhTb[(size_t)64 * 512];
__device__ float g_bias[1024];                    // b_ih + b_hh

// ---------------- helpers ----------------
__device__ __forceinline__ float sigm(float x) {
    return 1.0f / (1.0f + __expf(-x));
}
__device__ __forceinline__ unsigned hadd2b(unsigned a, unsigned b) {
    unsigned d; asm("add.rn.bf16x2 %0, %1, %2;" : "=r"(d) : "r"(a), "r"(b)); return d;
}
__device__ __forceinline__ unsigned tanh2b(unsigned a) {
    unsigned d; asm("tanh.approx.bf16x2 %0, %1;" : "=r"(d) : "r"(a)); return d;
}
__device__ __forceinline__ float b16lo(unsigned q) { return __uint_as_float(q << 16); }
__device__ __forceinline__ float b16hi(unsigned q) { return __uint_as_float(q & 0xFFFF0000u); }
__device__ __forceinline__ unsigned packbf2(float lo, float hi) {
    unsigned d; asm("cvt.rn.bf16x2.f32 %0, %1, %2;" : "=r"(d) : "f"(hi), "f"(lo)); return d;
}
__device__ __forceinline__ void ldm4(unsigned* r, unsigned addr) {
    asm volatile("ldmatrix.sync.aligned.m8n8.x4.shared.b16 {%0,%1,%2,%3}, [%4];"
                 : "=r"(r[0]), "=r"(r[1]), "=r"(r[2]), "=r"(r[3]) : "r"(addr));
}
__device__ __forceinline__ void mma16816(float* d, const unsigned* a, unsigned b0, unsigned b1) {
    asm volatile(
        "mma.sync.aligned.m16n8k16.row.col.f32.bf16.bf16.f32 "
        "{%0,%1,%2,%3}, {%4,%5,%6,%7}, {%8,%9}, {%0,%1,%2,%3};"
        : "+f"(d[0]), "+f"(d[1]), "+f"(d[2]), "+f"(d[3])
        : "r"(a[0]), "r"(a[1]), "r"(a[2]), "r"(a[3]), "r"(b0), "r"(b1));
}
__device__ __forceinline__ void cp16(unsigned saddr, const void* g) {
    asm volatile("cp.async.cg.shared.global [%0], [%1], 16;" :: "r"(saddr), "l"(g));
}
__device__ __forceinline__ void stcs1(float* p, float v) {
    asm volatile("st.global.cs.f32 [%0], %1;" :: "l"(p), "f"(v));
}
__device__ __forceinline__ float ldcs1(const float* p) {
    float v; asm volatile("ld.global.cs.f32 %0, [%1];" : "=f"(v) : "l"(p)); return v;
}

// ---------------- init ----------------
__global__ void init_kernel() {
    int idx = blockIdx.x * 256 + threadIdx.x;
    g_h[0][idx] = 0.f;
    g_c[0][idx] = 0.f;
    int b = idx >> 8, j = idx & 255;
    g_Ahi[0][(size_t)b * 512 + 256 + j] = __float2bfloat16(0.f);
    g_Alo[0][(size_t)b * 512 + 256 + j] = __float2bfloat16(0.f);
}

// ---------------- prep: split W, transpose W_h, combine biases ----------------
__global__ void prep_kernel(const float* __restrict__ W_ih, const float* __restrict__ W_hh,
                            const float* __restrict__ b_ih, const float* __restrict__ b_hh,
                            const float* __restrict__ W_h) {
    int idx = blockIdx.x * 256 + threadIdx.x;
    int n = idx >> 9, k = idx & 511;
    float v = (k < 256) ? W_ih[n * 256 + k] : W_hh[n * 256 + (k - 256)];
    __nv_bfloat16 hi = __float2bfloat16(v);
    g_Whi[idx] = hi;
    g_Wlo[idx] = __float2bfloat16(v - __bfloat162float(hi));
    if (idx < 64 * 512) {
        int u = idx >> 9, kk = idx & 511;
        g_WhTb[idx] = __float2bfloat16(W_h[kk * 64 + u]);   // W_h is (2H, T)
    }
    if (idx < 1024) g_bias[idx] = b_ih[idx] + b_hh[idx];
}

// ---------------- pre_fs (bf16, transposed out): [b][i][u] ----------------
__global__ void prefs_kernel(const float* __restrict__ FS,
                             const float* __restrict__ W_fs,
                             const float* __restrict__ b_fs) {
    __shared__ float sFS[21 * 256];
    __shared__ float sW[21 * 64];
    __shared__ float sbf[64];
    int b = blockIdx.x, tid = threadIdx.x;
    if (tid < 64) sbf[tid] = b_fs[tid];
    __syncthreads();
    float acc[64];
#pragma unroll
    for (int u = 0; u < 64; u++) acc[u] = sbf[u];

    for (int cch = 0; cch < 3; cch++) {
        int t0 = cch * 21;
        __syncthreads();
        for (int x = tid; x < 21 * 256; x += 256) sFS[x] = FS[(size_t)b * TM1 * II + t0 * II + x];
        for (int x = tid; x < 21 * 64; x += 256) sW[x] = W_fs[t0 * 64 + x];
        __syncthreads();
        for (int t = 0; t < 21; t++) {
            float xv = sFS[t * 256 + tid];
            const float4* w4 = (const float4*)(sW + t * 64);
#pragma unroll
            for (int j = 0; j < 16; j++) {
                float4 w = w4[j];
                acc[4 * j + 0] += xv * w.x;
                acc[4 * j + 1] += xv * w.y;
                acc[4 * j + 2] += xv * w.z;
                acc[4 * j + 3] += xv * w.w;
            }
        }
    }
    // transposed write: row (b, i=tid), 64 contiguous u as bf16 (128 B)
    uint4* dst = (uint4*)(g_prefsb + (((size_t)b * 256 + tid) << 6));
#pragma unroll
    for (int ch = 0; ch < 8; ch++) {
        uint4 v;
        v.x = packbf2(acc[ch * 8 + 0], acc[ch * 8 + 1]);
        v.y = packbf2(acc[ch * 8 + 2], acc[ch * 8 + 3]);
        v.z = packbf2(acc[ch * 8 + 4], acc[ch * 8 + 5]);
        v.w = packbf2(acc[ch * 8 + 6], acc[ch * 8 + 7]);
        dst[ch] = v;
    }
}

// ---------------- attention step: 4 batches/block, 512 threads, packed-bf16 path ----------------
__global__ __launch_bounds__(512) void attn_kernel(
        const float* __restrict__ FS, const float* __restrict__ yh,
        const float* __restrict__ b_h, const float* __restrict__ W_fs,
        const float* __restrict__ W_attn,
        float* __restrict__ out1, int t, int cur) {
    __shared__ float4 hc4[512];          // [k] -> 4 batches
    __shared__ float sp[8][4][64];
    __shared__ unsigned s2p[4][32];      // packed bf16x2 score per (bb, u-pair)
    __shared__ float2 wa2[32];
    __shared__ float red[16][2];

    int b0 = blockIdx.x * 4;
    int tid = threadIdx.x;
    const float* hcur = g_h[cur];
    const float* ccur = g_c[cur];

    for (int x = tid; x < 2048; x += 512) {
        int k = x >> 2, bb = x & 3;
        ((float*)hc4)[x] = (k < 256) ? hcur[(b0 + bb) * 256 + k]
                                     : ccur[(b0 + bb) * 256 + (k - 256)];
    }
    if (tid < 32) wa2[tid] = make_float2(W_attn[2 * tid], W_attn[2 * tid + 1]);
    __syncthreads();

    // phase 1: score = [h,c] @ W_h  (u = tid%64, q = tid/64 -> 64-k chunk), bf16 W_hT
    {
        int u = tid & 63, q = tid >> 6;
        const uint4* wp = (const uint4*)(g_WhTb + (size_t)u * 512 + q * 64);
        float p0 = 0, p1 = 0, p2 = 0, p3 = 0;
#pragma unroll
        for (int ch = 0; ch < 8; ch++) {
            uint4 wv = wp[ch];
            unsigned wq[4] = {wv.x, wv.y, wv.z, wv.w};
#pragma unroll
            for (int e = 0; e < 4; e++) {
                int k = q * 64 + ch * 8 + e * 2;
                float wlo = b16lo(wq[e]), whi = b16hi(wq[e]);
                float4 h0 = hc4[k], h1 = hc4[k + 1];
                p0 = fmaf(h0.x, wlo, p0); p0 = fmaf(h1.x, whi, p0);
                p1 = fmaf(h0.y, wlo, p1); p1 = fmaf(h1.y, whi, p1);
                p2 = fmaf(h0.z, wlo, p2); p2 = fmaf(h1.z, whi, p2);
                p3 = fmaf(h0.w, wlo, p3); p3 = fmaf(h1.w, whi, p3);
            }
        }
        sp[q][0][u] = p0; sp[q][1][u] = p1; sp[q][2][u] = p2; sp[q][3][u] = p3;
    }
    __syncthreads();
    if (tid < 128) {
        int bb = tid >> 5, up = tid & 31;
        int u0 = 2 * up, u1 = u0 + 1;
        float y = yh[(b0 + bb) * TM1 + t];
        float sA = b_h[u0] + y * W_fs[63 * 64 + u0];
        float sB = b_h[u1] + y * W_fs[63 * 64 + u1];
#pragma unroll
        for (int q = 0; q < 8; q++) { sA += sp[q][bb][u0]; sB += sp[q][bb][u1]; }
        s2p[bb][up] = packbf2(sA, sB);
    }
    __syncthreads();

    // phase 2: logits; thread = (g = tid/256, i = tid%256) handling batches b0+g, b0+g+2
    int g = tid >> 8, i = tid & 255;
    const uint4* pf0 = (const uint4*)(g_prefsb + (((size_t)(b0 + g) * 256 + i) << 6));
    const uint4* pf1 = (const uint4*)(g_prefsb + (((size_t)(b0 + g + 2) * 256 + i) << 6));
    float a0 = 0.f, a1 = 0.f;
#pragma unroll
    for (int ch = 0; ch < 8; ch++) {
        uint4 P0 = pf0[ch], P1 = pf1[ch];
        unsigned q0[4] = {P0.x, P0.y, P0.z, P0.w};
        unsigned q1[4] = {P1.x, P1.y, P1.z, P1.w};
#pragma unroll
        for (int pr = 0; pr < 4; pr++) {
            int up = ch * 4 + pr;
            float2 w2 = wa2[up];
            unsigned t0 = tanh2b(hadd2b(q0[pr], s2p[g][up]));
            unsigned t1 = tanh2b(hadd2b(q1[pr], s2p[g + 2][up]));
            a0 = fmaf(b16lo(t0), w2.x, a0); a0 = fmaf(b16hi(t0), w2.y, a0);
            a1 = fmaf(b16lo(t1), w2.x, a1); a1 = fmaf(b16hi(t1), w2.y, a1);
        }
    }

    // softmax over i (256 threads per (g, slot)); logits bounded -> no max subtraction
    float e0 = __expf(a0), e1 = __expf(a1);
    float s0 = e0, s1 = e1;
#pragma unroll
    for (int off = 16; off; off >>= 1) {
        s0 += __shfl_xor_sync(0xffffffffu, s0, off);
        s1 += __shfl_xor_sync(0xffffffffu, s1, off);
    }
    int lane = tid & 31, wid = tid >> 5;
    if (lane == 0) { red[wid][0] = s0; red[wid][1] = s1; }
    __syncthreads();
    int base = g * 8;
    float t0s = 0.f, t1s = 0.f;
#pragma unroll
    for (int w = 0; w < 8; w++) { t0s += red[base + w][0]; t1s += red[base + w][1]; }
    float inv0 = 1.0f / t0s, inv1 = 1.0f / t1s;

    int bA = b0 + g, bC = b0 + g + 2;
    float fs0 = ldcs1(FS + (size_t)bA * TM1 * II + t * II + i);
    float fs1 = ldcs1(FS + (size_t)bC * TM1 * II + t * II + i);
    float w0 = e0 * inv0 * fs0;
    float w1 = e1 * inv1 * fs1;
    stcs1(out1 + (size_t)bA * TM1 * II + t * II + i, w0);
    stcs1(out1 + (size_t)bC * TM1 * II + t * II + i, w1);

    __nv_bfloat16 h0 = __float2bfloat16(w0);
    g_Ahi[cur][(size_t)bA * 512 + i] = h0;
    g_Alo[cur][(size_t)bA * 512 + i] = __float2bfloat16(w0 - __bfloat162float(h0));
    __nv_bfloat16 h1 = __float2bfloat16(w1);
    g_Ahi[cur][(size_t)bC * 512 + i] = h1;
    g_Alo[cur][(size_t)bC * 512 + i] = __float2bfloat16(w1 - __bfloat162float(h1));
}

// ---------------- gates GEMM (bf16-split tensor core, cp.async 2-stage) + LSTM ----------------
#define SAP 40   // smem k-stride (bf16 elems)
#define ABYTES (128 * SAP * 2)            // 10240
#define BBYTES (64 * SAP * 2)             // 5120
#define STAGEB (2 * ABYTES + 2 * BBYTES)  // 30720
__global__ __launch_bounds__(256) void gates_mma_kernel(float* __restrict__ out2, int t, int cur) {
    extern __shared__ char dynsm[];
    unsigned sbase = (unsigned)__cvta_generic_to_shared(dynsm);

    int j0 = blockIdx.x * 16;
    int b0 = blockIdx.y * 128;
    int tid = threadIdx.x;
    int w = tid >> 5, l = tid & 31;
    int lp = l & 7, quad = l >> 3;
    int wrow = w * 16;

    const __nv_bfloat16* Ahi = g_Ahi[cur];
    const __nv_bfloat16* Alo = g_Alo[cur];

    unsigned aoff = (unsigned)(((wrow + lp + (quad & 1) * 8) * SAP + (quad >> 1) * 8) * 2);
    unsigned boff4[4];
#pragma unroll
    for (int q4 = 0; q4 < 4; q4++)
        boff4[q4] = (unsigned)(((q4 * 16 + lp + (quad >> 1) * 8) * SAP + (quad & 1) * 8) * 2);

    int ar0 = tid >> 2, ac4 = tid & 3;
    int br = tid >> 2, bc4 = tid & 3;
    int bng = (br >> 4) * 256 + j0 + (br & 15);

    int colb = (l & 3) * 2;
    float bias[2][2][4];
#pragma unroll
    for (int jb = 0; jb < 2; jb++)
#pragma unroll
        for (int ch = 0; ch < 2; ch++) {
            int j = j0 + jb * 8 + colb + ch;
#pragma unroll
            for (int g = 0; g < 4; g++) bias[jb][ch][g] = g_bias[g * 256 + j];
        }

    float acc[8][4];
#pragma unroll
    for (int nt = 0; nt < 8; nt++)
#pragma unroll
        for (int d = 0; d < 4; d++) acc[nt][d] = 0.f;

    auto issue = [&](int kc, int st) {
        int k0 = kc * 32;
        unsigned so = sbase + st * STAGEB;
#pragma unroll
        for (int it = 0; it < 2; it++) {
            int r = ar0 + it * 64;
            size_t goff = (size_t)(b0 + r) * 512 + k0 + ac4 * 8;
            unsigned sm = so + (unsigned)((r * SAP + ac4 * 8) * 2);
            cp16(sm, Ahi + goff);
            cp16(sm + ABYTES, Alo + goff);
        }
        size_t woff = (size_t)bng * 512 + k0 + bc4 * 8;
        unsigned smb = so + 2 * ABYTES + (unsigned)((br * SAP + bc4 * 8) * 2);
        cp16(smb, g_Whi + woff);
        cp16(smb + BBYTES, g_Wlo + woff);
        asm volatile("cp.async.commit_group;");
    };

    issue(0, 0);
    for (int kc = 0; kc < 16; kc++) {
        int st = kc & 1;
        if (kc + 1 < 16) {
            issue(kc + 1, st ^ 1);
            asm volatile("cp.async.wait_group 1;");
        } else {
            asm volatile("cp.async.wait_group 0;");
        }
        __syncthreads();

        unsigned so = sbase + st * STAGEB;
        unsigned uAhi = so + aoff, uAlo = so + ABYTES + aoff;
#pragma unroll
        for (int ks = 0; ks < 2; ks++) {
            unsigned kb = ks * 32;
            unsigned ahi[4], alo[4];
            ldm4(ahi, uAhi + kb);
            ldm4(alo, uAlo + kb);
            unsigned bh[4][4], bl[4][4];
#pragma unroll
            for (int q4 = 0; q4 < 4; q4++) {
                ldm4(bh[q4], so + 2 * ABYTES + boff4[q4] + kb);
                ldm4(bl[q4], so + 2 * ABYTES + BBYTES + boff4[q4] + kb);
            }
#pragma unroll
            for (int q4 = 0; q4 < 4; q4++) {
                mma16816(acc[2 * q4],     ahi, bh[q4][0], bh[q4][1]);
                mma16816(acc[2 * q4],     ahi, bl[q4][0], bl[q4][1]);
                mma16816(acc[2 * q4],     alo, bh[q4][0], bh[q4][1]);
                mma16816(acc[2 * q4 + 1], ahi, bh[q4][2], bh[q4][3]);
                mma16816(acc[2 * q4 + 1], ahi, bl[q4][2], bl[q4][3]);
                mma16816(acc[2 * q4 + 1], alo, bh[q4][2], bh[q4][3]);
            }
        }
        __syncthreads();
    }

    // epilogue: LSTM in registers
    const float* ccur = g_c[cur];
    float* hnxt = g_h[cur ^ 1];
    float* cnxt = g_c[cur ^ 1];
    __nv_bfloat16* Ahn = g_Ahi[cur ^ 1];
    __nv_bfloat16* Aln = g_Alo[cur ^ 1];
    int row = l >> 2;
#pragma unroll
    for (int jb = 0; jb < 2; jb++)
#pragma unroll
        for (int ch = 0; ch < 2; ch++) {
            int j = j0 + jb * 8 + colb + ch;
#pragma unroll
            for (int rh = 0; rh < 2; rh++) {
                int d = rh * 2 + ch;
                int b = b0 + wrow + row + rh * 8;
                float iv = acc[0 + jb][d] + bias[jb][ch][0];
                float fv = acc[2 + jb][d] + bias[jb][ch][1];
                float gv = acc[4 + jb][d] + bias[jb][ch][2];
                float ov = acc[6 + jb][d] + bias[jb][ch][3];
                int bidx = b * 256 + j;
                float cold = ccur[bidx];
                float cnew = sigm(fv) * cold + sigm(iv) * tanhf(gv);
                float hnew = sigm(ov) * tanhf(cnew);
                cnxt[bidx] = cnew;
                hnxt[bidx] = hnew;
                __nv_bfloat16 hh = __float2bfloat16(hnew);
                Ahn[(size_t)b * 512 + 256 + j] = hh;
                Aln[(size_t)b * 512 + 256 + j] = __float2bfloat16(hnew - __bfloat162float(hh));
                stcs1(out2 + (size_t)b * TM1 * 256 + t * 256 + j, hnew);
            }
        }
}

// ---------------- launch ----------------
extern "C" void kernel_launch(void* const* d_in, const int* in_sizes, int n_in,
                              void* d_out, int out_size) {
    const float* FS     = (const float*)d_in[0];
    const float* yh     = (const float*)d_in[1];
    const float* W_h    = (const float*)d_in[2];
    const float* b_h    = (const float*)d_in[3];
    const float* W_fs   = (const float*)d_in[4];
    const float* b_fs   = (const float*)d_in[5];
    const float* W_attn = (const float*)d_in[6];
    // d_in[7] = b_attn: cancels inside softmax, unused
    const float* W_ih   = (const float*)d_in[8];
    const float* W_hh   = (const float*)d_in[9];
    const float* b_ih   = (const float*)d_in[10];
    const float* b_hh   = (const float*)d_in[11];

    float* out1 = (float*)d_out;                       // input_weighted (B, 63, I)
    float* out2 = out1 + (size_t)BB * TM1 * II;        // input_encoded (B, 63, H)

    static int attr_done = 0;
    if (!attr_done) {
        cudaFuncSetAttribute(gates_mma_kernel,
                             cudaFuncAttributeMaxDynamicSharedMemorySize, 2 * STAGEB);
        attr_done = 1;
    }

    init_kernel<<<BB * HH / 256, 256>>>();
    prep_kernel<<<1024 * 512 / 256, 256>>>(W_ih, W_hh, b_ih, b_hh, W_h);
    prefs_kernel<<<BB, 256>>>(FS, W_fs, b_fs);
    for (int t = 0; t < TM1; t++) {
        int cur = t & 1;
        attn_kernel<<<BB / 4, 512>>>(FS, yh, b_h, W_fs, W_attn, out1, t, cur);
        gates_mma_kernel<<<dim3(16, 8), 256, 2 * STAGEB>>>(out2, t, cur);
    }
}

// round 10
// speedup vs baseline: 1.0535x; 1.0535x over previous
#include <cuda_runtime.h>
#include <cuda_bf16.h>

#define BB 1024
#define II 256
#define HH 256
#define TT 64
#define TM1 63

// ---------------- device scratch (static: no allocation allowed) ----------------
__device__ __nv_bfloat16 g_prefsb[(size_t)BB * TT * II];   // [b][u][i] bf16, 32 MB (coalesced i)
__device__ float g_h[2][BB * HH];
__device__ float g_c[2][BB * HH];
// A = [w_in | h] as bf16 hi/lo split, double-buffered on the h half: [slot][b][k0..511]
__device__ __nv_bfloat16 g_Ahi[2][(size_t)BB * 512];
__device__ __nv_bfloat16 g_Alo[2][(size_t)BB * 512];
// W = [W_ih | W_hh] rows n=gate*256+j, k 0..511, bf16 hi/lo split
__device__ __nv_bfloat16 g_Whi[(size_t)1024 * 512];
__device__ __nv_bfloat16 g_Wlo[(size_t)1024 * 512];
// W_h transposed [u][k] bf16
__device__ __nv_bfloat16 g_WhTb[(size_t)64 * 512];
__device__ float g_bias[1024];                    // b_ih + b_hh

// ---------------- helpers ----------------
__device__ __forceinline__ float sigm(float x) {
    return 1.0f / (1.0f + __expf(-x));
}
__device__ __forceinline__ unsigned hadd2b(unsigned a, unsigned b) {
    unsigned d; asm("add.rn.bf16x2 %0, %1, %2;" : "=r"(d) : "r"(a), "r"(b)); return d;
}
__device__ __forceinline__ unsigned tanh2b(unsigned a) {
    unsigned d; asm("tanh.approx.bf16x2 %0, %1;" : "=r"(d) : "r"(a)); return d;
}
__device__ __forceinline__ float b16lo(unsigned q) { return __uint_as_float(q << 16); }
__device__ __forceinline__ float b16hi(unsigned q) { return __uint_as_float(q & 0xFFFF0000u); }
__device__ __forceinline__ unsigned packbf2(float lo, float hi) {
    unsigned d; asm("cvt.rn.bf16x2.f32 %0, %1, %2;" : "=r"(d) : "f"(hi), "f"(lo)); return d;
}
__device__ __forceinline__ void ldm4(unsigned* r, unsigned addr) {
    asm volatile("ldmatrix.sync.aligned.m8n8.x4.shared.b16 {%0,%1,%2,%3}, [%4];"
                 : "=r"(r[0]), "=r"(r[1]), "=r"(r[2]), "=r"(r[3]) : "r"(addr));
}
__device__ __forceinline__ void mma16816(float* d, const unsigned* a, unsigned b0, unsigned b1) {
    asm volatile(
        "mma.sync.aligned.m16n8k16.row.col.f32.bf16.bf16.f32 "
        "{%0,%1,%2,%3}, {%4,%5,%6,%7}, {%8,%9}, {%0,%1,%2,%3};"
        : "+f"(d[0]), "+f"(d[1]), "+f"(d[2]), "+f"(d[3])
        : "r"(a[0]), "r"(a[1]), "r"(a[2]), "r"(a[3]), "r"(b0), "r"(b1));
}
__device__ __forceinline__ void cp16(unsigned saddr, const void* g) {
    asm volatile("cp.async.cg.shared.global [%0], [%1], 16;" :: "r"(saddr), "l"(g));
}
__device__ __forceinline__ void stcs1(float* p, float v) {
    asm volatile("st.global.cs.f32 [%0], %1;" :: "l"(p), "f"(v));
}
__device__ __forceinline__ float ldcs1(const float* p) {
    float v; asm volatile("ld.global.cs.f32 %0, [%1];" : "=f"(v) : "l"(p)); return v;
}

// ---------------- init ----------------
__global__ void init_kernel() {
    int idx = blockIdx.x * 256 + threadIdx.x;
    g_h[0][idx] = 0.f;
    g_c[0][idx] = 0.f;
    int b = idx >> 8, j = idx & 255;
    g_Ahi[0][(size_t)b * 512 + 256 + j] = __float2bfloat16(0.f);
    g_Alo[0][(size_t)b * 512 + 256 + j] = __float2bfloat16(0.f);
}

// ---------------- prep: split W, transpose W_h, combine biases ----------------
__global__ void prep_kernel(const float* __restrict__ W_ih, const float* __restrict__ W_hh,
                            const float* __restrict__ b_ih, const float* __restrict__ b_hh,
                            const float* __restrict__ W_h) {
    int idx = blockIdx.x * 256 + threadIdx.x;
    int n = idx >> 9, k = idx & 511;
    float v = (k < 256) ? W_ih[n * 256 + k] : W_hh[n * 256 + (k - 256)];
    __nv_bfloat16 hi = __float2bfloat16(v);
    g_Whi[idx] = hi;
    g_Wlo[idx] = __float2bfloat16(v - __bfloat162float(hi));
    if (idx < 64 * 512) {
        int u = idx >> 9, kk = idx & 511;
        g_WhTb[idx] = __float2bfloat16(W_h[kk * 64 + u]);   // W_h is (2H, T)
    }
    if (idx < 1024) g_bias[idx] = b_ih[idx] + b_hh[idx];
}

// ---------------- pre_fs (bf16 out, [b][u][i]) ----------------
__global__ void prefs_kernel(const float* __restrict__ FS,
                             const float* __restrict__ W_fs,
                             const float* __restrict__ b_fs) {
    __shared__ float sFS[21 * 256];
    __shared__ float sW[21 * 64];
    __shared__ float sbf[64];
    int b = blockIdx.x, tid = threadIdx.x;
    if (tid < 64) sbf[tid] = b_fs[tid];
    __syncthreads();
    float acc[64];
#pragma unroll
    for (int u = 0; u < 64; u++) acc[u] = sbf[u];

    for (int cch = 0; cch < 3; cch++) {
        int t0 = cch * 21;
        __syncthreads();
        for (int x = tid; x < 21 * 256; x += 256) sFS[x] = FS[(size_t)b * TM1 * II + t0 * II + x];
        for (int x = tid; x < 21 * 64; x += 256) sW[x] = W_fs[t0 * 64 + x];
        __syncthreads();
        for (int t = 0; t < 21; t++) {
            float xv = sFS[t * 256 + tid];
            const float4* w4 = (const float4*)(sW + t * 64);
#pragma unroll
            for (int j = 0; j < 16; j++) {
                float4 w = w4[j];
                acc[4 * j + 0] += xv * w.x;
                acc[4 * j + 1] += xv * w.y;
                acc[4 * j + 2] += xv * w.z;
                acc[4 * j + 3] += xv * w.w;
            }
        }
    }
#pragma unroll
    for (int u = 0; u < 64; u++)
        g_prefsb[((size_t)b * 64 + u) * 256 + tid] = __float2bfloat16(acc[u]);
}

// ---------------- attention step: 2 batches/block, 256 threads, packed-bf16 tanh ----------------
__global__ __launch_bounds__(256) void attn_kernel(
        const float* __restrict__ FS, const float* __restrict__ yh,
        const float* __restrict__ b_h, const float* __restrict__ W_fs,
        const float* __restrict__ W_attn,
        float* __restrict__ out1, int t, int cur) {
    __shared__ float2 hc2[512];          // [k] -> (b0, b0+1)
    __shared__ float sp[4][2][64];
    __shared__ unsigned s2d[2][64];      // bf16x2 dup of score per (bb, u)
    __shared__ float wa[64];
    __shared__ float2 part[2][2][128];   // [u-half][bb][i-pair]
    __shared__ float red[2][4];

    int b0 = blockIdx.x * 2;
    int tid = threadIdx.x;
    const float* hcur = g_h[cur];
    const float* ccur = g_c[cur];

    for (int x = tid; x < 1024; x += 256) {
        int k = x >> 1, bb = x & 1;
        ((float*)hc2)[x] = (k < 256) ? hcur[(b0 + bb) * 256 + k]
                                     : ccur[(b0 + bb) * 256 + (k - 256)];
    }
    if (tid < 64) wa[tid] = W_attn[tid];
    __syncthreads();

    // phase 1: score = [h,c] @ W_h  (u = tid%64, q = tid/64 -> 128-k chunk), bf16 W_hT
    {
        int u = tid & 63, q = tid >> 6;
        const uint4* wp = (const uint4*)(g_WhTb + (size_t)u * 512 + q * 128);
        float p0 = 0.f, p1 = 0.f;
#pragma unroll
        for (int ch = 0; ch < 16; ch++) {
            uint4 wv = wp[ch];
            unsigned wq[4] = {wv.x, wv.y, wv.z, wv.w};
#pragma unroll
            for (int e = 0; e < 4; e++) {
                int k = q * 128 + ch * 8 + e * 2;
                float wlo = b16lo(wq[e]), whi = b16hi(wq[e]);
                float2 h0 = hc2[k], h1 = hc2[k + 1];
                p0 = fmaf(h0.x, wlo, p0); p0 = fmaf(h1.x, whi, p0);
                p1 = fmaf(h0.y, wlo, p1); p1 = fmaf(h1.y, whi, p1);
            }
        }
        sp[q][0][u] = p0; sp[q][1][u] = p1;
    }
    __syncthreads();
    if (tid < 128) {
        int bb = tid >> 6, u = tid & 63;
        float y = yh[(b0 + bb) * TM1 + t];
        float s = b_h[u] + y * W_fs[63 * 64 + u];
#pragma unroll
        for (int q = 0; q < 4; q++) s += sp[q][bb][u];
        s2d[bb][u] = packbf2(s, s);
    }
    __syncthreads();

    // phase 2: logits; uo = u-half (32 u), ip = i-pair; coalesced LDG.32 per u-row
    int uo = tid >> 7, ip = tid & 127;
#pragma unroll
    for (int bb = 0; bb < 2; bb++) {
        const unsigned* pf = (const unsigned*)
            (g_prefsb + (((size_t)(b0 + bb) * 64 + uo * 32) << 8)) + ip;
        float ax = 0.f, ay = 0.f;
#pragma unroll
        for (int uu = 0; uu < 32; uu++) {
            int u = uo * 32 + uu;
            unsigned q = pf[uu << 7];
            unsigned tt = tanh2b(hadd2b(q, s2d[bb][u]));
            float wv = wa[u];
            ax = fmaf(b16lo(tt), wv, ax);
            ay = fmaf(b16hi(tt), wv, ay);
        }
        part[uo][bb][ip] = make_float2(ax, ay);
    }
    __syncthreads();

    // phase 3: combine halves, softmax over i (logits bounded -> no max subtraction)
    {
        int bb = tid >> 7, ipp = tid & 127;
        int lane = tid & 31, wg = (tid >> 5) & 3;
        float2 lg;
        lg.x = part[0][bb][ipp].x + part[1][bb][ipp].x;
        lg.y = part[0][bb][ipp].y + part[1][bb][ipp].y;
        float ex = __expf(lg.x), ey = __expf(lg.y);
        float s2 = ex + ey;
#pragma unroll
        for (int off = 16; off; off >>= 1) s2 += __shfl_xor_sync(0xffffffffu, s2, off);
        if (lane == 0) red[bb][wg] = s2;
        __syncthreads();
        float inv = 1.0f / ((red[bb][0] + red[bb][1]) + (red[bb][2] + red[bb][3]));
        int gb = b0 + bb;
        float fs0 = ldcs1(FS + (size_t)gb * TM1 * II + t * II + 2 * ipp);
        float fs1 = ldcs1(FS + (size_t)gb * TM1 * II + t * II + 2 * ipp + 1);
        float w0 = ex * inv * fs0;
        float w1 = ey * inv * fs1;
        stcs1(out1 + (size_t)gb * TM1 * II + t * II + 2 * ipp, w0);
        stcs1(out1 + (size_t)gb * TM1 * II + t * II + 2 * ipp + 1, w1);
        __nv_bfloat162 hi2, lo2;
        hi2.x = __float2bfloat16(w0);
        hi2.y = __float2bfloat16(w1);
        lo2.x = __float2bfloat16(w0 - __bfloat162float(hi2.x));
        lo2.y = __float2bfloat16(w1 - __bfloat162float(hi2.y));
        *(__nv_bfloat162*)(g_Ahi[cur] + (size_t)gb * 512 + 2 * ipp) = hi2;
        *(__nv_bfloat162*)(g_Alo[cur] + (size_t)gb * 512 + 2 * ipp) = lo2;
    }
}

// ---------------- gates GEMM (bf16-split tensor core, cp.async 2-stage) + LSTM ----------------
#define SAP 40   // smem k-stride (bf16 elems)
#define ABYTES (128 * SAP * 2)            // 10240
#define BBYTES (64 * SAP * 2)             // 5120
#define STAGEB (2 * ABYTES + 2 * BBYTES)  // 30720
__global__ __launch_bounds__(256) void gates_mma_kernel(float* __restrict__ out2, int t, int cur) {
    extern __shared__ char dynsm[];
    unsigned sbase = (unsigned)__cvta_generic_to_shared(dynsm);

    int j0 = blockIdx.x * 16;
    int b0 = blockIdx.y * 128;
    int tid = threadIdx.x;
    int w = tid >> 5, l = tid & 31;
    int lp = l & 7, quad = l >> 3;
    int wrow = w * 16;

    const __nv_bfloat16* Ahi = g_Ahi[cur];
    const __nv_bfloat16* Alo = g_Alo[cur];

    unsigned aoff = (unsigned)(((wrow + lp + (quad & 1) * 8) * SAP + (quad >> 1) * 8) * 2);
    unsigned boff4[4];
#pragma unroll
    for (int q4 = 0; q4 < 4; q4++)
        boff4[q4] = (unsigned)(((q4 * 16 + lp + (quad >> 1) * 8) * SAP + (quad & 1) * 8) * 2);

    int ar0 = tid >> 2, ac4 = tid & 3;
    int br = tid >> 2, bc4 = tid & 3;
    int bng = (br >> 4) * 256 + j0 + (br & 15);

    int colb = (l & 3) * 2;
    float bias[2][2][4];
#pragma unroll
    for (int jb = 0; jb < 2; jb++)
#pragma unroll
        for (int ch = 0; ch < 2; ch++) {
            int j = j0 + jb * 8 + colb + ch;
#pragma unroll
            for (int g = 0; g < 4; g++) bias[jb][ch][g] = g_bias[g * 256 + j];
        }

    float acc[8][4];
#pragma unroll
    for (int nt = 0; nt < 8; nt++)
#pragma unroll
        for (int d = 0; d < 4; d++) acc[nt][d] = 0.f;

    auto issue = [&](int kc, int st) {
        int k0 = kc * 32;
        unsigned so = sbase + st * STAGEB;
#pragma unroll
        for (int it = 0; it < 2; it++) {
            int r = ar0 + it * 64;
            size_t goff = (size_t)(b0 + r) * 512 + k0 + ac4 * 8;
            unsigned sm = so + (unsigned)((r * SAP + ac4 * 8) * 2);
            cp16(sm, Ahi + goff);
            cp16(sm + ABYTES, Alo + goff);
        }
        size_t woff = (size_t)bng * 512 + k0 + bc4 * 8;
        unsigned smb = so + 2 * ABYTES + (unsigned)((br * SAP + bc4 * 8) * 2);
        cp16(smb, g_Whi + woff);
        cp16(smb + BBYTES, g_Wlo + woff);
        asm volatile("cp.async.commit_group;");
    };

    issue(0, 0);
    for (int kc = 0; kc < 16; kc++) {
        int st = kc & 1;
        if (kc + 1 < 16) {
            issue(kc + 1, st ^ 1);
            asm volatile("cp.async.wait_group 1;");
        } else {
            asm volatile("cp.async.wait_group 0;");
        }
        __syncthreads();

        unsigned so = sbase + st * STAGEB;
        unsigned uAhi = so + aoff, uAlo = so + ABYTES + aoff;
#pragma unroll
        for (int ks = 0; ks < 2; ks++) {
            unsigned kb = ks * 32;
            unsigned ahi[4], alo[4];
            ldm4(ahi, uAhi + kb);
            ldm4(alo, uAlo + kb);
            unsigned bh[4][4], bl[4][4];
#pragma unroll
            for (int q4 = 0; q4 < 4; q4++) {
                ldm4(bh[q4], so + 2 * ABYTES + boff4[q4] + kb);
                ldm4(bl[q4], so + 2 * ABYTES + BBYTES + boff4[q4] + kb);
            }
#pragma unroll
            for (int q4 = 0; q4 < 4; q4++) {
                mma16816(acc[2 * q4],     ahi, bh[q4][0], bh[q4][1]);
                mma16816(acc[2 * q4],     ahi, bl[q4][0], bl[q4][1]);
                mma16816(acc[2 * q4],     alo, bh[q4][0], bh[q4][1]);
                mma16816(acc[2 * q4 + 1], ahi, bh[q4][2], bh[q4][3]);
                mma16816(acc[2 * q4 + 1], ahi, bl[q4][2], bl[q4][3]);
                mma16816(acc[2 * q4 + 1], alo, bh[q4][2], bh[q4][3]);
            }
        }
        __syncthreads();
    }

    // epilogue: LSTM in registers
    const float* ccur = g_c[cur];
    float* hnxt = g_h[cur ^ 1];
    float* cnxt = g_c[cur ^ 1];
    __nv_bfloat16* Ahn = g_Ahi[cur ^ 1];
    __nv_bfloat16* Aln = g_Alo[cur ^ 1];
    int row = l >> 2;
#pragma unroll
    for (int jb = 0; jb < 2; jb++)
#pragma unroll
        for (int ch = 0; ch < 2; ch++) {
            int j = j0 + jb * 8 + colb + ch;
#pragma unroll
            for (int rh = 0; rh < 2; rh++) {
                int d = rh * 2 + ch;
                int b = b0 + wrow + row + rh * 8;
                float iv = acc[0 + jb][d] + bias[jb][ch][0];
                float fv = acc[2 + jb][d] + bias[jb][ch][1];
                float gv = acc[4 + jb][d] + bias[jb][ch][2];
                float ov = acc[6 + jb][d] + bias[jb][ch][3];
                int bidx = b * 256 + j;
                float cold = ccur[bidx];
                float cnew = sigm(fv) * cold + sigm(iv) * tanhf(gv);
                float hnew = sigm(ov) * tanhf(cnew);
                cnxt[bidx] = cnew;
                hnxt[bidx] = hnew;
                __nv_bfloat16 hh = __float2bfloat16(hnew);
                Ahn[(size_t)b * 512 + 256 + j] = hh;
                Aln[(size_t)b * 512 + 256 + j] = __float2bfloat16(hnew - __bfloat162float(hh));
                stcs1(out2 + (size_t)b * TM1 * 256 + t * 256 + j, hnew);
            }
        }
}

// ---------------- launch ----------------
extern "C" void kernel_launch(void* const* d_in, const int* in_sizes, int n_in,
                              void* d_out, int out_size) {
    const float* FS     = (const float*)d_in[0];
    const float* yh     = (const float*)d_in[1];
    const float* W_h    = (const float*)d_in[2];
    const float* b_h    = (const float*)d_in[3];
    const float* W_fs   = (const float*)d_in[4];
    const float* b_fs   = (const float*)d_in[5];
    const float* W_attn = (const float*)d_in[6];
    // d_in[7] = b_attn: cancels inside softmax, unused
    const float* W_ih   = (const float*)d_in[8];
    const float* W_hh   = (const float*)d_in[9];
    const float* b_ih   = (const float*)d_in[10];
    const float* b_hh   = (const float*)d_in[11];

    float* out1 = (float*)d_out;                       // input_weighted (B, 63, I)
    float* out2 = out1 + (size_t)BB * TM1 * II;        // input_encoded (B, 63, H)

    static int attr_done = 0;
    if (!attr_done) {
        cudaFuncSetAttribute(gates_mma_kernel,
                             cudaFuncAttributeMaxDynamicSharedMemorySize, 2 * STAGEB);
        attr_done = 1;
    }

    init_kernel<<<BB * HH / 256, 256>>>();
    prep_kernel<<<1024 * 512 / 256, 256>>>(W_ih, W_hh, b_ih, b_hh, W_h);
    prefs_kernel<<<BB, 256>>>(FS, W_fs, b_fs);
    for (int t = 0; t < TM1; t++) {
        int cur = t & 1;
        attn_kernel<<<BB / 2, 256>>>(FS, yh, b_h, W_fs, W_attn, out1, t, cur);
        gates_mma_kernel<<<dim3(16, 8), 256, 2 * STAGEB>>>(out2, t, cur);
    }
}